// round 1
// baseline (speedup 1.0000x reference)
#include <cuda_runtime.h>
#include <cstdint>

#define EPSV 1e-5f
typedef unsigned long long ull;

#define NB 32
#define NC 512
#define ND 128
#define NM 3136
#define NH 56
#define NW 56

// ---------------- scratch (static device globals; no runtime alloc) ----------
__device__ __align__(16) float g_y[NB*ND*NM];     // relu(bn1(conv1))   51.4 MB
__device__ __align__(16) float g_s[NB*ND*NM];     // bn3(conv2)         51.4 MB
__device__ float g_ymean[NB*ND];                  // row sums of y
__device__ __align__(16) float g_cov[NB*ND*ND];   // raw y*y^T sums
__device__ __align__(16) float g_sp[NB*ND*64];    // 8x8 pooled s
__device__ float g_catt[NB*NC];
__device__ float g_patt[NB*64];

// ---------------- f32x2 packed-FMA helpers (Blackwell 2x fp32 rate) ----------
__device__ __forceinline__ ull pk2(float lo, float hi){
    ull r; asm("mov.b64 %0,{%1,%2};" : "=l"(r) : "f"(lo), "f"(hi)); return r;
}
__device__ __forceinline__ void fma2(ull& d, ull a, ull b){
    asm("fma.rn.f32x2 %0,%1,%2,%0;" : "+l"(d) : "l"(a), "l"(b));
}
__device__ __forceinline__ float2 up2(ull v){
    float2 r; asm("mov.b64 {%0,%1},%2;" : "=f"(r.x), "=f"(r.y) : "l"(v)); return r;
}

// ---------------- zero scratch accumulators ----------------------------------
__global__ void k_zero(){
    int i = blockIdx.x*256 + threadIdx.x;
    if (i < NB*ND*ND) g_cov[i]   = 0.f;
    if (i < NB*ND)    g_ymean[i] = 0.f;
}

// ---------------- fused dual 1x1 conv + bias + BN (+relu) + row-sum ----------
// grid (25, 2, 32): x = m-tile, y = which conv (0: wdr->g_y, 1: wdrs->g_s), z = batch
__global__ void __launch_bounds__(256,2) k_conv(
    const float* __restrict__ x,
    const float* __restrict__ wdr,  const float* __restrict__ bdr,
    const float* __restrict__ g1,   const float* __restrict__ be1,
    const float* __restrict__ m1,   const float* __restrict__ v1,
    const float* __restrict__ wdrs, const float* __restrict__ bdrs,
    const float* __restrict__ g3,   const float* __restrict__ be3,
    const float* __restrict__ m3,   const float* __restrict__ v3)
{
    const int b  = blockIdx.z;
    const int ot = blockIdx.y;
    const int m0 = blockIdx.x * 128;
    const int tid = threadIdx.x;
    const int tx = tid & 15, ty = tid >> 4;

    __shared__ __align__(16) float As[2][16][132];
    __shared__ __align__(16) float Bs[2][16][132];

    const float* __restrict__ W  = ot ? wdrs : wdr;
    const float* __restrict__ xb = x + (size_t)b * ((size_t)NC*NM);

    ull acc[8][4];
#pragma unroll
    for (int i=0;i<8;i++)
#pragma unroll
        for (int j=0;j<4;j++) acc[i][j] = 0ULL;

    float4 ra[2], rb[2];

    auto loadg = [&](int k0){
#pragma unroll
        for (int r=0;r<2;r++){
            int li = tid*2+r;
            ra[r] = *(const float4*)(W + (li>>2)*NC + k0 + (li&3)*4);
        }
#pragma unroll
        for (int r=0;r<2;r++){
            int li = tid + r*256;
            int kk = li>>5, nq = (li&31)*4;
            int m = m0 + nq;
            if (m < NM){
                float4 v = *(const float4*)(xb + (size_t)(k0+kk)*NM + m);
                v.x=fmaxf(v.x,0.f); v.y=fmaxf(v.y,0.f);
                v.z=fmaxf(v.z,0.f); v.w=fmaxf(v.w,0.f);
                rb[r]=v;
            } else rb[r]=make_float4(0.f,0.f,0.f,0.f);
        }
    };
    auto stores = [&](int bf){
#pragma unroll
        for (int r=0;r<2;r++){
            int li = tid*2+r;
            int o = li>>2, kq=(li&3)*4;
            As[bf][kq+0][o]=ra[r].x; As[bf][kq+1][o]=ra[r].y;
            As[bf][kq+2][o]=ra[r].z; As[bf][kq+3][o]=ra[r].w;
        }
#pragma unroll
        for (int r=0;r<2;r++){
            int li = tid + r*256;
            int kk = li>>5, nq=(li&31)*4;
            *(float4*)&Bs[bf][kk][nq] = rb[r];
        }
    };

    loadg(0); stores(0); __syncthreads();
    int bf = 0;
    for (int k0=0;k0<NC;k0+=16){
        bool more = (k0+16)<NC;
        if (more) loadg(k0+16);
#pragma unroll
        for (int k=0;k<16;k++){
            float4 a0 = *(const float4*)&As[bf][k][ty*4];
            float4 a1 = *(const float4*)&As[bf][k][64+ty*4];
            ull ap[8];
            ap[0]=pk2(a0.x,a0.x); ap[1]=pk2(a0.y,a0.y);
            ap[2]=pk2(a0.z,a0.z); ap[3]=pk2(a0.w,a0.w);
            ap[4]=pk2(a1.x,a1.x); ap[5]=pk2(a1.y,a1.y);
            ap[6]=pk2(a1.z,a1.z); ap[7]=pk2(a1.w,a1.w);
            const ull* b0p = (const ull*)&Bs[bf][k][tx*4];
            const ull* b1p = (const ull*)&Bs[bf][k][64+tx*4];
            ull bp[4] = { b0p[0], b0p[1], b1p[0], b1p[1] };
#pragma unroll
            for (int i=0;i<8;i++)
#pragma unroll
                for (int j=0;j<4;j++) fma2(acc[i][j], ap[i], bp[j]);
        }
        if (more) stores(bf^1);
        __syncthreads();
        bf ^= 1;
    }

    const float* __restrict__ bias = ot ? bdrs : bdr;
    const float* __restrict__ gg = ot ? g3 : g1;
    const float* __restrict__ bb = ot ? be3 : be1;
    const float* __restrict__ mm = ot ? m3 : m1;
    const float* __restrict__ vv = ot ? v3 : v1;
    float* __restrict__ outb = (ot ? g_s : g_y) + (size_t)b*ND*NM;

    const int mA = m0 + tx*4;
    const int mB = m0 + 64 + tx*4;

#pragma unroll
    for (int i=0;i<8;i++){
        int o = (i<4) ? (ty*4+i) : (64 + ty*4 + (i-4));
        float sc = gg[o]*rsqrtf(vv[o]+EPSV);
        float sh = bb[o] - mm[o]*sc;
        float bi = bias[o];
        float v[8];
        float2 p;
        p=up2(acc[i][0]); v[0]=p.x; v[1]=p.y;
        p=up2(acc[i][1]); v[2]=p.x; v[3]=p.y;
        p=up2(acc[i][2]); v[4]=p.x; v[5]=p.y;
        p=up2(acc[i][3]); v[6]=p.x; v[7]=p.y;
#pragma unroll
        for (int j=0;j<8;j++) v[j] = (v[j]+bi)*sc + sh;
        if (ot==0){
#pragma unroll
            for (int j=0;j<8;j++) v[j] = fmaxf(v[j], 0.f);
        }
        float rsum = 0.f;
        if (mA < NM){
            *(float4*)(outb + (size_t)o*NM + mA) = make_float4(v[0],v[1],v[2],v[3]);
            rsum += v[0]+v[1]+v[2]+v[3];
        }
        if (mB < NM){
            *(float4*)(outb + (size_t)o*NM + mB) = make_float4(v[4],v[5],v[6],v[7]);
            rsum += v[4]+v[5]+v[6]+v[7];
        }
        if (ot==0){
#pragma unroll
            for (int off=8; off>0; off>>=1)
                rsum += __shfl_down_sync(0xffffffffu, rsum, off, 16);
            if (tx==0) atomicAdd(&g_ymean[b*ND + o], rsum);
        }
    }
}

// ---------------- channel covariance: g_cov[b] += y[b] * y[b]^T (split-K) ----
// grid (7, 32): x = K-chunk (448 each), y = batch
__global__ void __launch_bounds__(256,2) k_cov()
{
    const int b  = blockIdx.y;
    const int kb = blockIdx.x * 448;
    const int tid = threadIdx.x;
    const int tx = tid & 15, ty = tid >> 4;
    const float* __restrict__ yb = g_y + (size_t)b*ND*NM;

    __shared__ __align__(16) float Ys[2][16][132];
    ull acc[8][4];
#pragma unroll
    for (int i=0;i<8;i++)
#pragma unroll
        for (int j=0;j<4;j++) acc[i][j]=0ULL;

    float4 ra[2];
    auto loadg = [&](int k0){
#pragma unroll
        for (int r=0;r<2;r++){
            int li = tid*2+r;
            ra[r] = *(const float4*)(yb + (size_t)(li>>2)*NM + kb + k0 + (li&3)*4);
        }
    };
    auto stores = [&](int bf){
#pragma unroll
        for (int r=0;r<2;r++){
            int li = tid*2+r;
            int d = li>>2, kq=(li&3)*4;
            Ys[bf][kq+0][d]=ra[r].x; Ys[bf][kq+1][d]=ra[r].y;
            Ys[bf][kq+2][d]=ra[r].z; Ys[bf][kq+3][d]=ra[r].w;
        }
    };

    loadg(0); stores(0); __syncthreads();
    int bf=0;
    for (int k0=0;k0<448;k0+=16){
        bool more = (k0+16)<448;
        if (more) loadg(k0+16);
#pragma unroll
        for (int k=0;k<16;k++){
            float4 a0 = *(const float4*)&Ys[bf][k][ty*4];
            float4 a1 = *(const float4*)&Ys[bf][k][64+ty*4];
            ull ap[8];
            ap[0]=pk2(a0.x,a0.x); ap[1]=pk2(a0.y,a0.y);
            ap[2]=pk2(a0.z,a0.z); ap[3]=pk2(a0.w,a0.w);
            ap[4]=pk2(a1.x,a1.x); ap[5]=pk2(a1.y,a1.y);
            ap[6]=pk2(a1.z,a1.z); ap[7]=pk2(a1.w,a1.w);
            const ull* b0p = (const ull*)&Ys[bf][k][tx*4];
            const ull* b1p = (const ull*)&Ys[bf][k][64+tx*4];
            ull bp[4] = {b0p[0],b0p[1],b1p[0],b1p[1]};
#pragma unroll
            for (int i=0;i<8;i++)
#pragma unroll
                for (int j=0;j<4;j++) fma2(acc[i][j], ap[i], bp[j]);
        }
        if (more) stores(bf^1);
        __syncthreads();
        bf^=1;
    }

    float* cb = g_cov + (size_t)b*ND*ND;
#pragma unroll
    for (int i=0;i<8;i++){
        int ro = (i<4)? ty*4+i : 64+ty*4+(i-4);
#pragma unroll
        for (int j=0;j<4;j++){
            float2 p = up2(acc[i][j]);
            int co = (j<2)? (tx*4 + j*2) : (64 + tx*4 + (j-2)*2);
            atomicAdd(&cb[ro*ND+co],   p.x);
            atomicAdd(&cb[ro*ND+co+1], p.y);
        }
    }
}

// ---------------- 8x8 average pooling of s ------------------------------------
// grid 4096 = (b,d), 256 threads
__global__ void k_pool(){
    const int bd = blockIdx.x;
    const int t = threadIdx.x;
    __shared__ float sb[NM];
    const float* sp = g_s + (size_t)bd*NM;
    for (int i=t;i<NM;i+=256) sb[i]=sp[i];
    __syncthreads();
    if (t<64){
        int gh=t>>3, gw=t&7;
        float sum=0.f;
#pragma unroll
        for (int i=0;i<7;i++)
#pragma unroll
            for (int j=0;j<7;j++)
                sum += sb[(gh*7+i)*NW + gw*7 + j];
        g_sp[bd*64+t] = sum*(1.f/49.f);
    }
}

// ---------------- channel attention: cov -> bn2 -> wrow -> wfc -> sigmoid -----
// grid 32 (batch), 256 threads
__global__ void k_catt(const float* __restrict__ g2, const float* __restrict__ be2,
                       const float* __restrict__ m2, const float* __restrict__ v2,
                       const float* __restrict__ wrow, const float* __restrict__ brow,
                       const float* __restrict__ wfc,  const float* __restrict__ bfc)
{
    const int b = blockIdx.x, t = threadIdx.x;
    __shared__ float meanS[ND];
    __shared__ float vchS[512];
    if (t < ND) meanS[t] = g_ymean[b*ND+t] * (1.f/(float)NM);
    __syncthreads();
    for (int f=t; f<512; f+=256){
        int i = f>>2;
        float mi = meanS[i];
        float sc = g2[i]*rsqrtf(v2[i]+EPSV);
        float sh = be2[i] - m2[i]*sc;
        const float* cr = g_cov + (size_t)b*ND*ND + i*ND;
        const float* wr = wrow + f*ND;
        float acc = 0.f;
        for (int k=0;k<ND;k++){
            float cb = (cr[k]*(1.f/(float)NM) - mi*meanS[k])*sc + sh;
            acc += cb * wr[k];
        }
        vchS[f] = acc + brow[f];
    }
    __syncthreads();
    for (int c=t; c<512; c+=256){
        const float* wf = wfc + c*512;
        float acc = bfc[c];
        for (int f=0; f<512; f++) acc += vchS[f]*wf[f];
        g_catt[b*512+c] = 1.f/(1.f+expf(-acc));
    }
}

// ---------------- spatial attention: sp -> covs -> bn4 -> wrows -> wfcs -------
// grid 32 (batch), 256 threads
__global__ void k_patt(const float* __restrict__ g4, const float* __restrict__ be4,
                       const float* __restrict__ m4, const float* __restrict__ v4,
                       const float* __restrict__ wrows, const float* __restrict__ brows,
                       const float* __restrict__ wfcs,  const float* __restrict__ bfcs)
{
    const int b = blockIdx.x, t = threadIdx.x;
    __shared__ float sf[ND*64];   // 32 KB; first 4 KB reused for bn'd covs
    __shared__ float cs[64];
    __shared__ float vsS[256];
    for (int i=t;i<ND*64;i+=256) sf[i] = g_sp[(size_t)b*ND*64 + i];
    __syncthreads();
    if (t<64){
        float s=0.f;
        for (int c=0;c<ND;c++) s += sf[c*64+t];
        cs[t]=s;
    }
    __syncthreads();
    const int tym = t>>4, txn = t&15;
    float a[4][4];
#pragma unroll
    for (int ii=0;ii<4;ii++)
#pragma unroll
        for (int jj=0;jj<4;jj++) a[ii][jj]=0.f;
    for (int c=0;c<ND;c++){
        const float* row = sf + c*64;
        float am[4], bv[4];
#pragma unroll
        for (int ii=0;ii<4;ii++) am[ii]=row[tym*4+ii];
#pragma unroll
        for (int jj=0;jj<4;jj++) bv[jj]=row[txn*4+jj];
#pragma unroll
        for (int ii=0;ii<4;ii++)
#pragma unroll
            for (int jj=0;jj<4;jj++) a[ii][jj] += am[ii]*bv[jj];
    }
    __syncthreads();   // everyone done reading sf
#pragma unroll
    for (int ii=0;ii<4;ii++){
        int m = tym*4+ii;
        float sc = g4[m]*rsqrtf(v4[m]+EPSV);
        float sh = be4[m] - m4[m]*sc;
        float cm = cs[m];
#pragma unroll
        for (int jj=0;jj<4;jj++){
            int n = txn*4+jj;
            float cv = (a[ii][jj] - cm*cs[n]*(1.f/64.f))*(1.f/64.f);
            sf[m*64+n] = cv*sc + sh;   // reuse sf as bn'd covs [64][64]
        }
    }
    __syncthreads();
    {
        int f = t;
        int i = f>>2;
        const float* wr = wrows + f*64;
        float acc = brows[f];
        for (int k=0;k<64;k++) acc += sf[i*64+k]*wr[k];
        vsS[f] = fmaxf(acc, 0.f);
    }
    __syncthreads();
    if (t<64){
        const float* wf = wfcs + t*256;
        float acc = bfcs[t];
        for (int f=0;f<256;f++) acc += vsS[f]*wf[f];
        g_patt[b*64+t] = 1.f/(1.f+expf(-acc));
    }
}

// ---------------- final: out = x*catt + relu(x*patt) --------------------------
// grid 50176 x 256, float4 per thread (rows of 56 are float4-aligned)
__global__ void k_final(const float* __restrict__ x, float* __restrict__ out){
    unsigned idx = (blockIdx.x*256u + threadIdx.x)*4u;
    unsigned bc  = idx / (unsigned)NM;          // b*512 + c
    unsigned pos = idx - bc*(unsigned)NM;
    unsigned b   = bc >> 9;
    unsigned h   = pos / (unsigned)NW;
    unsigned w   = pos - h*(unsigned)NW;
    float catt = g_catt[bc];
    const float* prow = g_patt + b*64u + (h/7u)*8u;
    float4 xv = *(const float4*)(x + idx);
    float p0 = prow[(w+0u)/7u];
    float p1 = prow[(w+1u)/7u];
    float p2 = prow[(w+2u)/7u];
    float p3 = prow[(w+3u)/7u];
    float4 o;
    o.x = xv.x*catt + fmaxf(xv.x*p0, 0.f);
    o.y = xv.y*catt + fmaxf(xv.y*p1, 0.f);
    o.z = xv.z*catt + fmaxf(xv.z*p2, 0.f);
    o.w = xv.w*catt + fmaxf(xv.w*p3, 0.f);
    *(float4*)(out + idx) = o;
}

// ---------------- launch ------------------------------------------------------
extern "C" void kernel_launch(void* const* d_in, const int* in_sizes, int n_in,
                              void* d_out, int out_size)
{
    (void)in_sizes; (void)n_in; (void)out_size;
    const float* x     = (const float*)d_in[0];
    const float* wdr   = (const float*)d_in[1];
    const float* bdr   = (const float*)d_in[2];
    const float* g1    = (const float*)d_in[3];
    const float* be1   = (const float*)d_in[4];
    const float* m1    = (const float*)d_in[5];
    const float* v1    = (const float*)d_in[6];
    const float* g2    = (const float*)d_in[7];
    const float* be2   = (const float*)d_in[8];
    const float* m2    = (const float*)d_in[9];
    const float* v2    = (const float*)d_in[10];
    const float* wrow  = (const float*)d_in[11];
    const float* brow  = (const float*)d_in[12];
    const float* wfc   = (const float*)d_in[13];
    const float* bfc   = (const float*)d_in[14];
    const float* wdrs  = (const float*)d_in[15];
    const float* bdrs  = (const float*)d_in[16];
    const float* g3    = (const float*)d_in[17];
    const float* be3   = (const float*)d_in[18];
    const float* m3    = (const float*)d_in[19];
    const float* v3    = (const float*)d_in[20];
    const float* g4    = (const float*)d_in[21];
    const float* be4   = (const float*)d_in[22];
    const float* m4    = (const float*)d_in[23];
    const float* v4    = (const float*)d_in[24];
    const float* wrows = (const float*)d_in[25];
    const float* brows = (const float*)d_in[26];
    const float* wfcs  = (const float*)d_in[27];
    const float* bfcs  = (const float*)d_in[28];
    float* out = (float*)d_out;

    k_zero<<<2048, 256>>>();
    dim3 gconv(25, 2, 32);
    k_conv<<<gconv, 256>>>(x, wdr, bdr, g1, be1, m1, v1,
                           wdrs, bdrs, g3, be3, m3, v3);
    dim3 gcov(7, 32);
    k_cov<<<gcov, 256>>>();
    k_pool<<<4096, 256>>>();
    k_catt<<<32, 256>>>(g2, be2, m2, v2, wrow, brow, wfc, bfc);
    k_patt<<<32, 256>>>(g4, be4, m4, v4, wrows, brows, wfcs, bfcs);
    k_final<<<50176, 256>>>(x, out);
}

// round 4
// speedup vs baseline: 1.2836x; 1.2836x over previous
#include <cuda_runtime.h>
#include <cuda_bf16.h>
#include <cstdint>

#define EPSV 1e-5f

#define NB 32
#define NC 512
#define ND 128
#define NM 3136
#define NH 56
#define NW 56

// ---------------- scratch (static device globals; no runtime alloc) ----------
__device__ __align__(16) float g_y[NB*ND*NM];     // relu(bn1(conv1))
__device__ __align__(16) float g_s[NB*ND*NM];     // bn3(conv2)
__device__ float g_ymean[NB*ND];                  // row sums of y
__device__ __align__(16) float g_cov[NB*ND*ND];   // raw y*y^T sums
__device__ __align__(16) float g_sp[NB*ND*64];    // 8x8 pooled s
__device__ float g_catt[NB*NC];
__device__ float g_patt[NB*64];

// ---------------- mma.sync helpers --------------------------------------------
__device__ __forceinline__ uint32_t smem_u32(const void* p){
    uint32_t a;
    asm("{ .reg .u64 t; cvta.to.shared.u64 t, %1; cvt.u32.u64 %0, t; }" : "=r"(a) : "l"(p));
    return a;
}
__device__ __forceinline__ void ldsm4(uint32_t* r, uint32_t a){
    asm volatile("ldmatrix.sync.aligned.m8n8.x4.shared.b16 {%0,%1,%2,%3}, [%4];"
        : "=r"(r[0]),"=r"(r[1]),"=r"(r[2]),"=r"(r[3]) : "r"(a));
}
__device__ __forceinline__ void ldsm4t(uint32_t* r, uint32_t a){
    asm volatile("ldmatrix.sync.aligned.m8n8.x4.trans.shared.b16 {%0,%1,%2,%3}, [%4];"
        : "=r"(r[0]),"=r"(r[1]),"=r"(r[2]),"=r"(r[3]) : "r"(a));
}
__device__ __forceinline__ void mma_bf16(float* c, const uint32_t* a, const uint32_t* b){
    asm volatile("mma.sync.aligned.m16n8k16.row.col.f32.bf16.bf16.f32 "
        "{%0,%1,%2,%3},{%4,%5,%6,%7},{%8,%9},{%0,%1,%2,%3};"
        : "+f"(c[0]),"+f"(c[1]),"+f"(c[2]),"+f"(c[3])
        : "r"(a[0]),"r"(a[1]),"r"(a[2]),"r"(a[3]), "r"(b[0]),"r"(b[1]));
}
__device__ __forceinline__ void split2(float v, unsigned short& h, unsigned short& lo){
    __nv_bfloat16 hb = __float2bfloat16(v);
    float hf = __bfloat162float(hb);
    __nv_bfloat16 lb = __float2bfloat16(v - hf);
    h  = __bfloat16_as_ushort(hb);
    lo = __bfloat16_as_ushort(lb);
}

// ---------------- zero scratch accumulators ----------------------------------
__global__ void k_zero(){
    int i = blockIdx.x*256 + threadIdx.x;
    if (i < NB*ND*ND) g_cov[i]   = 0.f;
    if (i < NB*ND)    g_ymean[i] = 0.f;
}

// =============== mma.sync fused 1x1 conv ======================================
// grid (25, 2, 32): x = 128-wide m tile, y = which conv, z = batch. 256 threads.
#define AROW 80                   // bytes per A row (32 bf16 = 64B + 16B pad; 16B-aligned rows)
#define ATB  (128*AROW)           // 10240
#define BROW 272                  // bytes per B row (128 bf16 + pad; 16B-aligned)
#define BTB  (32*BROW)            // 8704
#define CBUF (2*ATB + 2*BTB)      // per-buffer bytes
// offsets in buffer: AH=0, AL=ATB, BH=2*ATB, BL=2*ATB+BTB

__global__ void __launch_bounds__(256,1) k_conv_mma(
    const float* __restrict__ x,
    const float* __restrict__ wdr,  const float* __restrict__ bdr,
    const float* __restrict__ g1,   const float* __restrict__ be1,
    const float* __restrict__ m1,   const float* __restrict__ v1,
    const float* __restrict__ wdrs, const float* __restrict__ bdrs,
    const float* __restrict__ g3,   const float* __restrict__ be3,
    const float* __restrict__ m3,   const float* __restrict__ v3)
{
    extern __shared__ char smem[];
    const uint32_t sb = smem_u32(smem);
    const int tid = threadIdx.x, l = tid & 31, w = tid >> 5;
    const int b = blockIdx.z, ot = blockIdx.y, m0 = blockIdx.x*128;
    const int wr = w >> 2, wc = w & 3;
    const float* __restrict__ W  = ot ? wdrs : wdr;
    const float* __restrict__ xb = x + (size_t)b * ((size_t)NC*NM);

    float acc[4][4][4];
#pragma unroll
    for (int i=0;i<4;i++)
#pragma unroll
        for (int j=0;j<4;j++)
#pragma unroll
            for (int k=0;k<4;k++) acc[i][j][k]=0.f;

    float4 pa[4], pb[4];
    auto ldg = [&](int c0){
#pragma unroll
        for (int r=0;r<4;r++){
            int idx = r*256+tid;
            int o = idx>>3, k4 = idx&7;
            pa[r] = *(const float4*)(W + o*NC + c0 + k4*4);
        }
#pragma unroll
        for (int r=0;r<4;r++){
            int li = r*256+tid;
            int kk = li>>5, mq = (li&31)*4;
            if (m0+mq < NM){
                float4 v = *(const float4*)(xb + (size_t)(c0+kk)*NM + m0 + mq);
                v.x=fmaxf(v.x,0.f); v.y=fmaxf(v.y,0.f);
                v.z=fmaxf(v.z,0.f); v.w=fmaxf(v.w,0.f);
                pb[r]=v;
            } else pb[r]=make_float4(0.f,0.f,0.f,0.f);
        }
    };
    auto sts = [&](int buf){
        char* base = smem + buf*CBUF;
#pragma unroll
        for (int r=0;r<4;r++){
            int idx = r*256+tid;
            int o = idx>>3, k4 = idx&7;
            ushort4 hv, lv;
            split2(pa[r].x, hv.x, lv.x); split2(pa[r].y, hv.y, lv.y);
            split2(pa[r].z, hv.z, lv.z); split2(pa[r].w, hv.w, lv.w);
            *(ushort4*)(base + o*AROW + k4*8)       = hv;
            *(ushort4*)(base + ATB + o*AROW + k4*8) = lv;
        }
#pragma unroll
        for (int r=0;r<4;r++){
            int li = r*256+tid;
            int kk = li>>5, mq = (li&31)*4;
            ushort4 hv, lv;
            split2(pb[r].x, hv.x, lv.x); split2(pb[r].y, hv.y, lv.y);
            split2(pb[r].z, hv.z, lv.z); split2(pb[r].w, hv.w, lv.w);
            *(ushort4*)(base + 2*ATB + kk*BROW + mq*2)       = hv;
            *(ushort4*)(base + 2*ATB + BTB + kk*BROW + mq*2) = lv;
        }
    };

    ldg(0); sts(0); ldg(32);
    __syncthreads();
    int buf = 0;
    const int arow = wr*64 + (l&15);
    const int akad = ((l&16)?8:0);
    for (int c = 0; c < 16; c++){
        uint32_t abase = sb + buf*CBUF;
#pragma unroll
        for (int ks=0; ks<32; ks+=16){
            uint32_t AH[4][4], AL[4][4], BH[4][2], BL[4][2];
#pragma unroll
            for (int mi=0;mi<4;mi++){
                uint32_t ad = abase + (uint32_t)((arow + mi*16)*AROW + (ks+akad)*2);
                ldsm4(AH[mi], ad);
                ldsm4(AL[mi], ad + ATB);
            }
            // B: [k][m] rows, trans ldmatrix. x4 covers 2 n8-tiles.
#pragma unroll
            for (int p=0;p<2;p++){
                int n0 = wc*32 + p*16 + ((l&16)?8:0);
                uint32_t bd = abase + 2*ATB + (uint32_t)((ks + (l&15))*BROW + n0*2);
                uint32_t t4[4];
                ldsm4t(t4, bd);
                BH[2*p][0]=t4[0]; BH[2*p][1]=t4[1]; BH[2*p+1][0]=t4[2]; BH[2*p+1][1]=t4[3];
                ldsm4t(t4, bd + BTB);
                BL[2*p][0]=t4[0]; BL[2*p][1]=t4[1]; BL[2*p+1][0]=t4[2]; BL[2*p+1][1]=t4[3];
            }
#pragma unroll
            for (int mi=0;mi<4;mi++)
#pragma unroll
                for (int ni=0;ni<4;ni++){
                    mma_bf16(acc[mi][ni], AH[mi], BH[ni]);
                    mma_bf16(acc[mi][ni], AH[mi], BL[ni]);
                    mma_bf16(acc[mi][ni], AL[mi], BH[ni]);
                }
        }
        __syncthreads();
        if (c < 15){
            sts(buf^1);
            if (c < 14) ldg((c+2)*32);
            __syncthreads();
            buf ^= 1;
        }
    }

    // ---- epilogue: bias + BN (+relu) + store + row sums ----
    const float* gg = ot ? g3 : g1;
    const float* bb = ot ? be3 : be1;
    const float* mm = ot ? m3 : m1;
    const float* vv = ot ? v3 : v1;
    const float* bias = ot ? bdrs : bdr;
    float* __restrict__ dst = (ot ? g_s : g_y) + (size_t)b*ND*NM;
    const int r = l>>2, q = l&3;
#pragma unroll
    for (int mi=0;mi<4;mi++){
#pragma unroll
        for (int half=0; half<2; half++){
            int o = wr*64 + mi*16 + r + half*8;
            float sc = gg[o]*rsqrtf(vv[o]+EPSV);
            float ad = bias[o]*sc + bb[o] - mm[o]*sc;
            float rsum = 0.f;
#pragma unroll
            for (int ni=0;ni<4;ni++){
                int m = m0 + wc*32 + ni*8 + q*2;
                float v0 = acc[mi][ni][half*2+0]*sc + ad;
                float v1 = acc[mi][ni][half*2+1]*sc + ad;
                if (ot==0){ v0 = fmaxf(v0,0.f); v1 = fmaxf(v1,0.f); }
                if (m < NM){
                    *(float2*)(dst + (size_t)o*NM + m) = make_float2(v0, v1);
                    rsum += v0 + v1;
                }
            }
            if (ot==0){
                rsum += __shfl_xor_sync(0xffffffffu, rsum, 1);
                rsum += __shfl_xor_sync(0xffffffffu, rsum, 2);
                if (q==0) atomicAdd(&g_ymean[b*ND + o], rsum);
            }
        }
    }
}

// =============== mma.sync channel covariance ==================================
// grid (7, 32): x = 448-wide K chunk, y = batch. One tile serves A and B.
#define VBUF (2*ATB)      // per-buffer (H + L)

__global__ void __launch_bounds__(256,1) k_cov_mma()
{
    extern __shared__ char smem[];
    const uint32_t sb = smem_u32(smem);
    const int tid = threadIdx.x, l = tid & 31, w = tid >> 5;
    const int b = blockIdx.y, kb = blockIdx.x*448;
    const int wr = w >> 2, wc = w & 3;
    const float* __restrict__ yb = g_y + (size_t)b*ND*NM;

    float acc[4][4][4];
#pragma unroll
    for (int i=0;i<4;i++)
#pragma unroll
        for (int j=0;j<4;j++)
#pragma unroll
            for (int k=0;k<4;k++) acc[i][j][k]=0.f;

    float4 py[4];
    auto ldg = [&](int c0){
#pragma unroll
        for (int r=0;r<4;r++){
            int idx = r*256+tid;
            int d = idx>>3, m4 = idx&7;
            py[r] = *(const float4*)(yb + (size_t)d*NM + kb + c0 + m4*4);
        }
    };
    auto sts = [&](int buf){
        char* base = smem + buf*VBUF;
#pragma unroll
        for (int r=0;r<4;r++){
            int idx = r*256+tid;
            int d = idx>>3, m4 = idx&7;
            ushort4 hv, lv;
            split2(py[r].x, hv.x, lv.x); split2(py[r].y, hv.y, lv.y);
            split2(py[r].z, hv.z, lv.z); split2(py[r].w, hv.w, lv.w);
            *(ushort4*)(base + d*AROW + m4*8)       = hv;
            *(ushort4*)(base + ATB + d*AROW + m4*8) = lv;
        }
    };

    ldg(0); sts(0); ldg(32);
    __syncthreads();
    int buf = 0;
    const int arow = wr*64 + (l&15);
    const int brow = wc*32 + (l&15);
    const int akad = ((l&16)?8:0);
    for (int c = 0; c < 14; c++){
        uint32_t abase = sb + buf*VBUF;
#pragma unroll
        for (int ks=0; ks<32; ks+=16){
            uint32_t AH[4][4], AL[4][4], BH[4][2], BL[4][2];
#pragma unroll
            for (int mi=0;mi<4;mi++){
                uint32_t ad = abase + (uint32_t)((arow + mi*16)*AROW + (ks+akad)*2);
                ldsm4(AH[mi], ad);
                ldsm4(AL[mi], ad + ATB);
            }
            // B non-trans from the same [n][k] tile
#pragma unroll
            for (int p=0;p<2;p++){
                uint32_t bd = abase + (uint32_t)((brow + p*16)*AROW + (ks+akad)*2);
                uint32_t t4[4];
                ldsm4(t4, bd);
                BH[2*p][0]=t4[0]; BH[2*p][1]=t4[2]; BH[2*p+1][0]=t4[1]; BH[2*p+1][1]=t4[3];
                ldsm4(t4, bd + ATB);
                BL[2*p][0]=t4[0]; BL[2*p][1]=t4[2]; BL[2*p+1][0]=t4[1]; BL[2*p+1][1]=t4[3];
            }
#pragma unroll
            for (int mi=0;mi<4;mi++)
#pragma unroll
                for (int ni=0;ni<4;ni++){
                    mma_bf16(acc[mi][ni], AH[mi], BH[ni]);
                    mma_bf16(acc[mi][ni], AH[mi], BL[ni]);
                    mma_bf16(acc[mi][ni], AL[mi], BH[ni]);
                }
        }
        __syncthreads();
        if (c < 13){
            sts(buf^1);
            if (c < 12) ldg((c+2)*32);
            __syncthreads();
            buf ^= 1;
        }
    }

    float* cb = g_cov + (size_t)b*ND*ND;
    const int r = l>>2, q = l&3;
#pragma unroll
    for (int mi=0;mi<4;mi++){
#pragma unroll
        for (int half=0; half<2; half++){
            int ro = wr*64 + mi*16 + r + half*8;
#pragma unroll
            for (int ni=0;ni<4;ni++){
                int co = wc*32 + ni*8 + q*2;
                atomicAdd(&cb[ro*ND+co],   acc[mi][ni][half*2+0]);
                atomicAdd(&cb[ro*ND+co+1], acc[mi][ni][half*2+1]);
            }
        }
    }
}

// ---------------- 8x8 average pooling of s ------------------------------------
__global__ void k_pool(){
    const int bd = blockIdx.x;
    const int t = threadIdx.x;
    __shared__ float sb[NM];
    const float* sp = g_s + (size_t)bd*NM;
    for (int i=t;i<784;i+=256) ((float4*)sb)[i] = ((const float4*)sp)[i];
    __syncthreads();
    int cell = t>>2, sub = t&3;
    int gh = cell>>3, gw = cell&7;
    float sum = 0.f;
    for (int e = sub; e < 49; e += 4){
        int i = e/7, j = e-i*7;
        sum += sb[(gh*7+i)*NW + gw*7 + j];
    }
    sum += __shfl_xor_sync(0xffffffffu, sum, 1);
    sum += __shfl_xor_sync(0xffffffffu, sum, 2);
    if (sub==0) g_sp[bd*64+cell] = sum*(1.f/49.f);
}

// ---------------- channel attention -------------------------------------------
__global__ void k_catt(const float* __restrict__ g2, const float* __restrict__ be2,
                       const float* __restrict__ m2, const float* __restrict__ v2,
                       const float* __restrict__ wrow, const float* __restrict__ brow,
                       const float* __restrict__ wfc,  const float* __restrict__ bfc)
{
    const int b = blockIdx.x, t = threadIdx.x;
    __shared__ float meanS[ND];
    __shared__ float vchS[512];
    if (t < ND) meanS[t] = g_ymean[b*ND+t] * (1.f/(float)NM);
    __syncthreads();
    for (int f=t; f<512; f+=256){
        int i = f>>2;
        float mi = meanS[i];
        float sc = g2[i]*rsqrtf(v2[i]+EPSV);
        float sh = be2[i] - m2[i]*sc;
        const float* cr = g_cov + (size_t)b*ND*ND + i*ND;
        const float* wr = wrow + f*ND;
        float acc = 0.f;
        for (int k=0;k<ND;k++){
            float cb = (cr[k]*(1.f/(float)NM) - mi*meanS[k])*sc + sh;
            acc += cb * wr[k];
        }
        vchS[f] = acc + brow[f];
    }
    __syncthreads();
    for (int c=t; c<512; c+=256){
        const float* wf = wfc + c*512;
        float acc = bfc[c];
        for (int f=0; f<512; f++) acc += vchS[f]*wf[f];
        g_catt[b*512+c] = 1.f/(1.f+expf(-acc));
    }
}

// ---------------- spatial attention -------------------------------------------
__global__ void k_patt(const float* __restrict__ g4, const float* __restrict__ be4,
                       const float* __restrict__ m4, const float* __restrict__ v4,
                       const float* __restrict__ wrows, const float* __restrict__ brows,
                       const float* __restrict__ wfcs,  const float* __restrict__ bfcs)
{
    const int b = blockIdx.x, t = threadIdx.x;
    __shared__ float sf[ND*64];
    __shared__ float cs[64];
    __shared__ float vsS[256];
    for (int i=t;i<ND*64;i+=256) sf[i] = g_sp[(size_t)b*ND*64 + i];
    __syncthreads();
    if (t<64){
        float s=0.f;
        for (int c=0;c<ND;c++) s += sf[c*64+t];
        cs[t]=s;
    }
    __syncthreads();
    const int tym = t>>4, txn = t&15;
    float a[4][4];
#pragma unroll
    for (int ii=0;ii<4;ii++)
#pragma unroll
        for (int jj=0;jj<4;jj++) a[ii][jj]=0.f;
    for (int c=0;c<ND;c++){
        const float* row = sf + c*64;
        float am[4], bv[4];
#pragma unroll
        for (int ii=0;ii<4;ii++) am[ii]=row[tym*4+ii];
#pragma unroll
        for (int jj=0;jj<4;jj++) bv[jj]=row[txn*4+jj];
#pragma unroll
        for (int ii=0;ii<4;ii++)
#pragma unroll
            for (int jj=0;jj<4;jj++) a[ii][jj] += am[ii]*bv[jj];
    }
    __syncthreads();
#pragma unroll
    for (int ii=0;ii<4;ii++){
        int m = tym*4+ii;
        float sc = g4[m]*rsqrtf(v4[m]+EPSV);
        float sh = be4[m] - m4[m]*sc;
        float cm = cs[m];
#pragma unroll
        for (int jj=0;jj<4;jj++){
            int n = txn*4+jj;
            float cv = (a[ii][jj] - cm*cs[n]*(1.f/64.f))*(1.f/64.f);
            sf[m*64+n] = cv*sc + sh;
        }
    }
    __syncthreads();
    {
        int f = t;
        int i = f>>2;
        const float* wr = wrows + f*64;
        float acc = brows[f];
        for (int k=0;k<64;k++) acc += sf[i*64+k]*wr[k];
        vsS[f] = fmaxf(acc, 0.f);
    }
    __syncthreads();
    if (t<64){
        const float* wf = wfcs + t*256;
        float acc = bfcs[t];
        for (int f=0;f<256;f++) acc += vsS[f]*wf[f];
        g_patt[b*64+t] = 1.f/(1.f+expf(-acc));
    }
}

// ---------------- final: out = x*catt + relu(x*patt) --------------------------
__global__ void k_final(const float* __restrict__ x, float* __restrict__ out){
    unsigned idx = (blockIdx.x*256u + threadIdx.x)*4u;
    unsigned bc  = idx / (unsigned)NM;
    unsigned pos = idx - bc*(unsigned)NM;
    unsigned b   = bc >> 9;
    unsigned h   = pos / (unsigned)NW;
    unsigned w   = pos - h*(unsigned)NW;
    float catt = g_catt[bc];
    const float* prow = g_patt + b*64u + (h/7u)*8u;
    float4 xv = *(const float4*)(x + idx);
    float p0 = prow[(w+0u)/7u];
    float p1 = prow[(w+1u)/7u];
    float p2 = prow[(w+2u)/7u];
    float p3 = prow[(w+3u)/7u];
    float4 o;
    o.x = xv.x*catt + fmaxf(xv.x*p0, 0.f);
    o.y = xv.y*catt + fmaxf(xv.y*p1, 0.f);
    o.z = xv.z*catt + fmaxf(xv.z*p2, 0.f);
    o.w = xv.w*catt + fmaxf(xv.w*p3, 0.f);
    *(float4*)(out + idx) = o;
}

// ---------------- launch ------------------------------------------------------
extern "C" void kernel_launch(void* const* d_in, const int* in_sizes, int n_in,
                              void* d_out, int out_size)
{
    (void)in_sizes; (void)n_in; (void)out_size;
    const float* x     = (const float*)d_in[0];
    const float* wdr   = (const float*)d_in[1];
    const float* bdr   = (const float*)d_in[2];
    const float* g1    = (const float*)d_in[3];
    const float* be1   = (const float*)d_in[4];
    const float* m1    = (const float*)d_in[5];
    const float* v1    = (const float*)d_in[6];
    const float* g2    = (const float*)d_in[7];
    const float* be2   = (const float*)d_in[8];
    const float* m2    = (const float*)d_in[9];
    const float* v2    = (const float*)d_in[10];
    const float* wrow  = (const float*)d_in[11];
    const float* brow  = (const float*)d_in[12];
    const float* wfc   = (const float*)d_in[13];
    const float* bfc   = (const float*)d_in[14];
    const float* wdrs  = (const float*)d_in[15];
    const float* bdrs  = (const float*)d_in[16];
    const float* g3    = (const float*)d_in[17];
    const float* be3   = (const float*)d_in[18];
    const float* m3    = (const float*)d_in[19];
    const float* v3    = (const float*)d_in[20];
    const float* g4    = (const float*)d_in[21];
    const float* be4   = (const float*)d_in[22];
    const float* m4    = (const float*)d_in[23];
    const float* v4    = (const float*)d_in[24];
    const float* wrows = (const float*)d_in[25];
    const float* brows = (const float*)d_in[26];
    const float* wfcs  = (const float*)d_in[27];
    const float* bfcs  = (const float*)d_in[28];
    float* out = (float*)d_out;

    cudaFuncSetAttribute(k_conv_mma, cudaFuncAttributeMaxDynamicSharedMemorySize, 2*CBUF);
    cudaFuncSetAttribute(k_cov_mma,  cudaFuncAttributeMaxDynamicSharedMemorySize, 2*VBUF);

    k_zero<<<2048, 256>>>();
    dim3 gconv(25, 2, 32);
    k_conv_mma<<<gconv, 256, 2*CBUF>>>(x, wdr, bdr, g1, be1, m1, v1,
                                       wdrs, bdrs, g3, be3, m3, v3);
    dim3 gcov(7, 32);
    k_cov_mma<<<gcov, 256, 2*VBUF>>>();
    k_pool<<<4096, 256>>>();
    k_catt<<<32, 256>>>(g2, be2, m2, v2, wrow, brow, wfc, bfc);
    k_patt<<<32, 256>>>(g4, be4, m4, v4, wrows, brows, wfcs, bfcs);
    k_final<<<50176, 256>>>(x, out);
}